// round 4
// baseline (speedup 1.0000x reference)
#include <cuda_runtime.h>
#include <cstdint>

#define SEQ_LEN  120
#define BATCH    2048
#define INPUT    6
#define HID      64
#define GATES    256
#define LAYERS   4
#define TLEN     120
#define NB       16            // batch per CTA
#define NCTA     (BATCH / NB)  // 128
#define NTHR     512           // 2 kg * 64 hh * 4 bg

typedef unsigned long long ull;

// ---- gate-interleaved weights: [l][k][hh] float4 {Wi,Wf,Wg,Wo} -------------
__device__ float4 g_eW04[INPUT * HID];
__device__ float4 g_eWih4[(LAYERS - 1) * HID * HID];
__device__ float4 g_eWhh4[LAYERS * HID * HID];
__device__ float4 g_dW04[INPUT * HID];
__device__ float4 g_dWih4[(LAYERS - 1) * HID * HID];
__device__ float4 g_dWhh4[LAYERS * HID * HID];

#define N_W0   (INPUT * HID)
#define N_WIH  ((LAYERS - 1) * HID * HID)
#define N_WHH  (LAYERS * HID * HID)

__global__ void lstm36206574305735_pack(
    const float* __restrict__ eW0, const float* __restrict__ eWih,
    const float* __restrict__ eWhh, const float* __restrict__ dW0,
    const float* __restrict__ dWih, const float* __restrict__ dWhh)
{
    const int tot = 2 * (N_W0 + N_WIH + N_WHH);
    for (int idx = blockIdx.x * blockDim.x + threadIdx.x; idx < tot;
         idx += gridDim.x * blockDim.x) {
        int r = idx;
        const float* src; float4* dst; int Kdim;
        if (r < N_W0)                   { src = eW0;  dst = g_eW04;  Kdim = INPUT; }
        else if ((r -= N_W0)  < N_W0)   { src = dW0;  dst = g_dW04;  Kdim = INPUT; }
        else if ((r -= N_W0)  < N_WIH)  { src = eWih; dst = g_eWih4; Kdim = HID;   }
        else if ((r -= N_WIH) < N_WIH)  { src = dWih; dst = g_dWih4; Kdim = HID;   }
        else if ((r -= N_WIH) < N_WHH)  { src = eWhh; dst = g_eWhh4; Kdim = HID;   }
        else        { r -= N_WHH;         src = dWhh; dst = g_dWhh4; Kdim = HID;   }
        int per = Kdim * HID;
        int l = r / per, rr = r % per;
        int k = rr / HID, hh = rr % HID;
        const float* W = src + (size_t)l * GATES * Kdim;
        float4 v;
        v.x = W[(0 * HID + hh) * Kdim + k];
        v.y = W[(1 * HID + hh) * Kdim + k];
        v.z = W[(2 * HID + hh) * Kdim + k];
        v.w = W[(3 * HID + hh) * Kdim + k];
        dst[r] = v;
    }
}

// ---- helpers ----------------------------------------------------------------
__device__ __forceinline__ void ffma2(ull& d, ull a, ull b) {
    asm("fma.rn.f32x2 %0, %1, %2, %0;" : "+l"(d) : "l"(a), "l"(b));
}
__device__ __forceinline__ ull pk(float a, float b) {
    ull v; asm("mov.b64 %0, {%1, %2};" : "=l"(v) : "f"(a), "f"(b)); return v;
}
__device__ __forceinline__ float2 unpk(ull v) {
    float2 r; asm("mov.b64 {%0, %1}, %2;" : "=f"(r.x), "=f"(r.y) : "l"(v)); return r;
}
__device__ __forceinline__ float fsig(float x) {
    return __fdividef(1.0f, 1.0f + __expf(-x));
}
__device__ __forceinline__ float ftanh_(float x) {
    return 2.0f * fsig(2.0f * x) - 1.0f;
}

// gemv over dup'd h: per k = 1 LDG.128 + 2 LDS.128 + 8 FFMA2, no MOVs.
// W as ulonglong2: .x = (Wi,Wf) .y = (Wg,Wo); hs layout [k][32] with {h,h} pairs.
template <int K>
__device__ __forceinline__ void gemv_d(const ulonglong2* __restrict__ W,
                                       const float* __restrict__ hs,
                                       int hh, int bg,
                                       ull accif[4], ull accgo[4])
{
#pragma unroll 8
    for (int k = 0; k < K; k++) {
        ulonglong2 wv = W[k * HID + hh];
        ulonglong2 ha = *(const ulonglong2*)(hs + k * 32 + bg * 8);
        ulonglong2 hb = *(const ulonglong2*)(hs + k * 32 + bg * 8 + 4);
        ffma2(accif[0], wv.x, ha.x); ffma2(accgo[0], wv.y, ha.x);
        ffma2(accif[1], wv.x, ha.y); ffma2(accgo[1], wv.y, ha.y);
        ffma2(accif[2], wv.x, hb.x); ffma2(accgo[2], wv.y, hb.x);
        ffma2(accif[3], wv.x, hb.y); ffma2(accgo[3], wv.y, hb.y);
    }
}

// ---- smem layout (floats) ---------------------------------------------------
#define OFF_HD   0                               // [2][4][64][32]  dup'd h
#define SZ_HD    (2 * LAYERS * HID * 32)         // 16384
#define OFF_IN   (OFF_HD + SZ_HD)                // [6][32] dup'd input
#define SZ_IN    (INPUT * 32)                    // 192
#define OFF_LW   (OFF_IN + SZ_IN)                // [hh][i]
#define SZ_LW    (HID * INPUT)                   // 384
#define OFF_LB   (OFF_LW + SZ_LW)                // 8
#define OFF_BIAS (OFF_LB + 8)                    // [2][4][64] ulonglong2
#define SZ_BIAS  (2 * LAYERS * HID * 4)          // 2048 floats
#define OFF_PART (OFF_BIAS + SZ_BIAS)            // [256][9] ull (padded)
#define SZ_PART  (256 * 9 * 2)                   // 4608 floats
#define SMEM_FLOATS (OFF_PART + SZ_PART)
#define SMEM_BYTES  (SMEM_FLOATS * 4)

__global__ void __launch_bounds__(NTHR, 1)
lstm36206574305735_main(const float* __restrict__ x,
                        const float* __restrict__ eB,
                        const float* __restrict__ dB,
                        const float* __restrict__ linW,
                        const float* __restrict__ linB,
                        float* __restrict__ out)
{
    extern __shared__ float smem[];
    float* hd   = smem + OFF_HD;
    float* ind  = smem + OFF_IN;
    float* lw_s = smem + OFF_LW;
    float* lb_s = smem + OFF_LB;
    ulonglong2* bias_s = (ulonglong2*)(smem + OFF_BIAS);
    ull* part_s = (ull*)(smem + OFF_PART);       // [256][9]

    const int tid = threadIdx.x;
    const int kg  = tid >> 8;      // 0: Wih/input gemv + cell; 1: Whh gemv
    const int r   = tid & 255;
    const int hh  = r >> 2;        // 0..63
    const int bg  = r & 3;         // batch quad
    const int b0  = blockIdx.x * NB;

    for (int i = tid; i < SZ_HD; i += NTHR) hd[i] = 0.0f;
    for (int i = tid; i < HID * INPUT; i += NTHR) {
        int h2 = i / INPUT, ii = i % INPUT;
        lw_s[h2 * INPUT + ii] = linW[ii * HID + h2];
    }
    if (tid < INPUT) lb_s[tid] = linB[tid];
    for (int u = tid; u < 2 * LAYERS * HID; u += NTHR) {
        int phase = u >> 8, l = (u >> 6) & 3, hx = u & 63;
        const float* B = phase ? dB : eB;
        ulonglong2 v;
        v.x = pk(B[l * GATES + hx],           B[l * GATES + HID + hx]);
        v.y = pk(B[l * GATES + 2 * HID + hx], B[l * GATES + 3 * HID + hx]);
        bias_s[u] = v;
    }

    float c_reg[LAYERS][4];     // only kg0 uses
#pragma unroll
    for (int l = 0; l < LAYERS; l++)
#pragma unroll
        for (int bi = 0; bi < 4; bi++) c_reg[l][bi] = 0.0f;

    __syncthreads();

    const ulonglong2* eW0p  = (const ulonglong2*)g_eW04;
    const ulonglong2* eWihp = (const ulonglong2*)g_eWih4;
    const ulonglong2* eWhhp = (const ulonglong2*)g_eWhh4;
    const ulonglong2* dW0p  = (const ulonglong2*)g_dW04;
    const ulonglong2* dWihp = (const ulonglong2*)g_dWih4;
    const ulonglong2* dWhhp = (const ulonglong2*)g_dWhh4;

    auto step = [&](int phase, int w, const ulonglong2* W0p,
                    const ulonglong2* Wihp, const ulonglong2* Whhp) {
#pragma unroll
        for (int l = 0; l < LAYERS; l++) {
            ull accif[4], accgo[4];
            if (kg == 1) {
                // hidden-to-hidden gemv on h from previous step (buffer w^1)
#pragma unroll
                for (int bi = 0; bi < 4; bi++) { accif[bi] = 0ull; accgo[bi] = 0ull; }
                gemv_d<HID>(Whhp + l * HID * HID,
                            hd + (((w ^ 1) * LAYERS + l) * HID) * 32,
                            hh, bg, accif, accgo);
                ull* pr = part_s + r * 9;
#pragma unroll
                for (int i = 0; i < 4; i++) { pr[i] = accif[i]; pr[4 + i] = accgo[i]; }
            } else {
                ulonglong2 bv = bias_s[(phase * LAYERS + l) * HID + hh];
#pragma unroll
                for (int bi = 0; bi < 4; bi++) { accif[bi] = bv.x; accgo[bi] = bv.y; }
                if (l == 0) {
                    gemv_d<INPUT>(W0p, ind, hh, bg, accif, accgo);
                } else {
                    gemv_d<HID>(Wihp + (l - 1) * HID * HID,
                                hd + ((w * LAYERS + (l - 1)) * HID) * 32,
                                hh, bg, accif, accgo);
                }
            }
            __syncthreads();

            if (kg == 0) {
                const ull ONE = pk(1.0f, 1.0f);
                const ull* pr = part_s + r * 9;
#pragma unroll
                for (int i = 0; i < 4; i++) {
                    ffma2(accif[i], pr[i], ONE);
                    ffma2(accgo[i], pr[4 + i], ONE);
                }
                float hout[4];
#pragma unroll
                for (int bi = 0; bi < 4; bi++) {
                    float2 sif = unpk(accif[bi]);
                    float2 sgo = unpk(accgo[bi]);
                    float c = fmaf(fsig(sif.y), c_reg[l][bi],
                                   fsig(sif.x) * ftanh_(sgo.x));
                    c_reg[l][bi] = c;
                    hout[bi] = fsig(sgo.y) * ftanh_(c);
                }
                float* hrow = hd + ((w * LAYERS + l) * HID + hh) * 32 + bg * 8;
                *(float4*)hrow = make_float4(hout[0], hout[0], hout[1], hout[1]);
                *(float4*)(hrow + 4) = make_float4(hout[2], hout[2], hout[3], hout[3]);
            }
            __syncthreads();
        }
    };

    // -------- encoder --------
    for (int t = 0; t < SEQ_LEN; t++) {
        if (tid < INPUT * NB) {
            int b = tid / INPUT, i = tid % INPUT;
            float v = x[((size_t)t * BATCH + b0 + b) * INPUT + i];
            ind[i * 32 + 2 * b] = v;
            ind[i * 32 + 2 * b + 1] = v;
        }
        __syncthreads();
        step(0, t & 1, eW0p, eWihp, eWhhp);
    }
    // ind holds x[SEQ_LEN-1] — decoder seed

    // -------- decoder --------
    for (int t = 0; t < TLEN; t++) {
        int w = (SEQ_LEN + t) & 1;
        step(1, w, dW0p, dWihp, dWhhp);

        if (tid < INPUT * NB) {
            int b = tid / INPUT, i = tid % INPUT;
            const float* htop = hd + ((w * LAYERS + (LAYERS - 1)) * HID) * 32;
            float v = lb_s[i];
#pragma unroll 8
            for (int h2 = 0; h2 < HID; h2++)
                v += lw_s[h2 * INPUT + i] * htop[h2 * 32 + 2 * b];
            out[((size_t)t * BATCH + b0 + b) * INPUT + i] = v;
            ind[i * 32 + 2 * b] = v;
            ind[i * 32 + 2 * b + 1] = v;
        }
        __syncthreads();
    }
}

extern "C" void kernel_launch(void* const* d_in, const int* in_sizes, int n_in,
                              void* d_out, int out_size)
{
    const float* x    = (const float*)d_in[0];
    const float* eW0  = (const float*)d_in[1];
    const float* eWih = (const float*)d_in[2];
    const float* eWhh = (const float*)d_in[3];
    const float* eB   = (const float*)d_in[4];
    const float* dW0  = (const float*)d_in[5];
    const float* dWih = (const float*)d_in[6];
    const float* dWhh = (const float*)d_in[7];
    const float* dB   = (const float*)d_in[8];
    const float* linW = (const float*)d_in[9];
    const float* linB = (const float*)d_in[10];
    float* out = (float*)d_out;

    lstm36206574305735_pack<<<227, 256>>>(eW0, eWih, eWhh, dW0, dWih, dWhh);

    cudaFuncSetAttribute(lstm36206574305735_main,
                         cudaFuncAttributeMaxDynamicSharedMemorySize, SMEM_BYTES);
    lstm36206574305735_main<<<NCTA, NTHR, SMEM_BYTES>>>(x, eB, dB, linW, linB, out);
}

// round 5
// speedup vs baseline: 1.6896x; 1.6896x over previous
#include <cuda_runtime.h>
#include <cstdint>

#define SEQ_LEN  120
#define BATCH    2048
#define INPUT    6
#define HID      64
#define GATES    256
#define LAYERS   4
#define TLEN     120
#define NB       16
#define NCTA     (BATCH / NB)   // 128
#define NTHR     256

#define CHUNK_ROWS 32
#define CHUNK_F4   (CHUNK_ROWS * HID)     // 2048 float4
#define CHUNK_BYTES (CHUNK_F4 * 16)       // 32768
#define NSLOT      5
#define CPS        15                     // chunks per step
#define TOTALC     (240 * CPS)            // 3600

typedef unsigned long long ull;

// ---- flat periodic weight streams: [15 chunks][32 k][64 hh] float4{i,f,g,o}
__device__ float4 g_stream_e[CPS * CHUNK_F4];
__device__ float4 g_stream_d[CPS * CHUNK_F4];

__global__ void lstm36206574305735_pack(
    const float* __restrict__ eW0, const float* __restrict__ eWih,
    const float* __restrict__ eWhh, const float* __restrict__ dW0,
    const float* __restrict__ dWih, const float* __restrict__ dWhh)
{
    const int tot = 2 * CPS * CHUNK_F4;
    for (int idx = blockIdx.x * blockDim.x + threadIdx.x; idx < tot;
         idx += gridDim.x * blockDim.x) {
        int p  = idx / (CPS * CHUNK_F4);
        int r  = idx % (CPS * CHUNK_F4);
        int c  = r / CHUNK_F4;
        int rr = r % CHUNK_F4;
        int kc = rr / HID;
        int hh = rr % HID;
        const float* W0  = p ? dW0  : eW0;
        const float* Wih = p ? dWih : eWih;
        const float* Whh = p ? dWhh : eWhh;
        float4 v = make_float4(0.f, 0.f, 0.f, 0.f);
        if (c == 0) {                         // L0 input weights, k-padded
            if (kc < INPUT) {
                v.x = W0[(0 * HID + hh) * INPUT + kc];
                v.y = W0[(1 * HID + hh) * INPUT + kc];
                v.z = W0[(2 * HID + hh) * INPUT + kc];
                v.w = W0[(3 * HID + hh) * INPUT + kc];
            }
        } else {
            const float* W; int k;
            if (c <= 2) {                     // L0 Whh
                W = Whh;                      // layer 0
                k = (c - 1) * CHUNK_ROWS + kc;
            } else {
                int l  = (c - 3) / 4 + 1;
                int cc = (c - 3) % 4;
                if (cc < 2) { W = Wih + (size_t)(l - 1) * GATES * HID; k = cc * CHUNK_ROWS + kc; }
                else        { W = Whh + (size_t)l * GATES * HID;       k = (cc - 2) * CHUNK_ROWS + kc; }
            }
            v.x = W[(0 * HID + hh) * HID + k];
            v.y = W[(1 * HID + hh) * HID + k];
            v.z = W[(2 * HID + hh) * HID + k];
            v.w = W[(3 * HID + hh) * HID + k];
        }
        (p ? g_stream_d : g_stream_e)[r] = v;
    }
}

// ---- helpers ----------------------------------------------------------------
__device__ __forceinline__ void ffma2(ull& d, ull a, ull b) {
    asm("fma.rn.f32x2 %0, %1, %2, %0;" : "+l"(d) : "l"(a), "l"(b));
}
__device__ __forceinline__ ull dup2(float a) {
    ull v; asm("mov.b64 %0, {%1, %1};" : "=l"(v) : "f"(a)); return v;
}
__device__ __forceinline__ float2 unpk(ull v) {
    float2 r; asm("mov.b64 {%0, %1}, %2;" : "=f"(r.x), "=f"(r.y) : "l"(v)); return r;
}
__device__ __forceinline__ float fsig(float x) {
    return __fdividef(1.0f, 1.0f + __expf(-x));
}
__device__ __forceinline__ float ftanh_(float x) {
    return 2.0f * fsig(2.0f * x) - 1.0f;
}
__device__ __forceinline__ uint32_t smem_u32(const void* p) {
    uint32_t a;
    asm("{ .reg .u64 t; cvta.to.shared.u64 t, %1; cvt.u32.u64 %0, t; }"
        : "=r"(a) : "l"(p));
    return a;
}

__device__ __forceinline__ void issue_chunk_g(int G, uint32_t ring_u32, uint32_t mbar_u32) {
    if (G >= TOTALC) return;
    int s = G % NSLOT;
    const float4* src = (G < 120 * CPS ? g_stream_e : g_stream_d) + (size_t)(G % CPS) * CHUNK_F4;
    uint32_t mb = mbar_u32 + s * 8;
    asm volatile("mbarrier.arrive.expect_tx.shared.b64 _, [%0], %1;"
                 :: "r"(mb), "r"((uint32_t)CHUNK_BYTES) : "memory");
    asm volatile("cp.async.bulk.shared::cluster.global.mbarrier::complete_tx::bytes "
                 "[%0], [%1], %2, [%3];"
                 :: "r"(ring_u32 + (uint32_t)s * CHUNK_BYTES), "l"(src),
                    "r"((uint32_t)CHUNK_BYTES), "r"(mb) : "memory");
}

__device__ __forceinline__ void wait_parity(uint32_t mb, uint32_t parity) {
    asm volatile(
        "{\n\t"
        ".reg .pred P;\n\t"
        "WLOOP_%=:\n\t"
        "mbarrier.try_wait.parity.acquire.cta.shared::cta.b64 P, [%0], %1, 0x989680;\n\t"
        "@P bra WDONE_%=;\n\t"
        "bra WLOOP_%=;\n\t"
        "WDONE_%=:\n\t"
        "}"
        :: "r"(mb), "r"(parity) : "memory");
}

// gemv over one chunk from smem ring: per k = 2 LDS.128 + 4 movs + 8 FFMA2
template <int K>
__device__ __forceinline__ void gemv_s(const float4* __restrict__ wslot,
                                       const float* __restrict__ hs,
                                       int hh, int bg, ull acc[8])
{
#pragma unroll 8
    for (int k = 0; k < K; k++) {
        float4 w4 = wslot[k * HID + hh];
        ulonglong2 hv = *(const ulonglong2*)(hs + k * 16 + bg * 4);
        ull wi = dup2(w4.x), wf = dup2(w4.y), wg = dup2(w4.z), wo = dup2(w4.w);
        ffma2(acc[0], wi, hv.x); ffma2(acc[1], wi, hv.y);
        ffma2(acc[2], wf, hv.x); ffma2(acc[3], wf, hv.y);
        ffma2(acc[4], wg, hv.x); ffma2(acc[5], wg, hv.y);
        ffma2(acc[6], wo, hv.x); ffma2(acc[7], wo, hv.y);
    }
}

// ---- smem layout (bytes) ------------------------------------------------------
#define RING_B    0
#define RING_SZ   (NSLOT * CHUNK_BYTES)     // 163840
#define MBAR_B    RING_SZ                   // 40 bytes
#define FB_B      (RING_SZ + 64)            // 163904, 16-aligned
// float-region offsets (in floats from FB_B)
#define HD_F    0
#define SZ_HD   (2 * LAYERS * HID * 16)     // 8192
#define IND_F   (HD_F + SZ_HD)              // 8 rows x 16 = 128 (zero-padded)
#define LW_F    (IND_F + 128)               // 384
#define LB_F    (LW_F + 384)                // 8
#define BIAS_F  (LB_F + 8)                  // ull[2][4][64][4] = 4096 floats
#define SMEM_TOTAL_B (FB_B + (BIAS_F + 4096) * 4)   // 215136

__global__ void __launch_bounds__(NTHR, 1)
lstm36206574305735_main(const float* __restrict__ x,
                        const float* __restrict__ eB,
                        const float* __restrict__ dB,
                        const float* __restrict__ linW,
                        const float* __restrict__ linB,
                        float* __restrict__ out)
{
    extern __shared__ char sm[];
    float4* ring = (float4*)sm;
    const uint32_t ring_u = smem_u32(sm);
    const uint32_t mbar_u = ring_u + MBAR_B;
    float* fb   = (float*)(sm + FB_B);
    float* hd   = fb + HD_F;
    float* ind  = fb + IND_F;
    float* lw_s = fb + LW_F;
    float* lb_s = fb + LB_F;
    ull*   bias = (ull*)(fb + BIAS_F);

    const int tid = threadIdx.x;
    const int hh  = tid >> 2;
    const int bg  = tid & 3;
    const int b0  = blockIdx.x * NB;

    // ---- init ----
    if (tid == 0) {
        for (int s = 0; s < NSLOT; s++)
            asm volatile("mbarrier.init.shared.b64 [%0], 1;"
                         :: "r"(mbar_u + s * 8) : "memory");
        asm volatile("fence.proxy.async.shared::cta;" ::: "memory");
    }
    for (int i = tid; i < SZ_HD; i += NTHR) hd[i] = 0.0f;
    for (int i = tid; i < 128; i += NTHR) ind[i] = 0.0f;
    for (int i = tid; i < HID * INPUT; i += NTHR) {
        int h2 = i / INPUT, ii = i % INPUT;
        lw_s[h2 * INPUT + ii] = linW[ii * HID + h2];
    }
    if (tid < INPUT) lb_s[tid] = linB[tid];
    for (int u = tid; u < 2 * LAYERS * HID; u += NTHR) {
        int phase = u >> 8, l = (u >> 6) & 3, hx = u & 63;
        const float* B = phase ? dB : eB;
        bias[u * 4 + 0] = dup2(B[l * GATES + hx]);
        bias[u * 4 + 1] = dup2(B[l * GATES + HID + hx]);
        bias[u * 4 + 2] = dup2(B[l * GATES + 2 * HID + hx]);
        bias[u * 4 + 3] = dup2(B[l * GATES + 3 * HID + hx]);
    }
    __syncthreads();

    // initial prefetch: chunks 0..4
    if (tid == 0)
        for (int g = 0; g < NSLOT; g++) issue_chunk_g(g, ring_u, mbar_u);
    int Gi = NSLOT;
    unsigned par = 0;

    float c_reg[LAYERS][4];
#pragma unroll
    for (int l = 0; l < LAYERS; l++)
#pragma unroll
        for (int bi = 0; bi < 4; bi++) c_reg[l][bi] = 0.0f;

    const int  bb  = tid / INPUT;   // valid for tid < 96
    const int  ii  = tid % INPUT;
    const bool isx = tid < INPUT * NB;
    float xreg = 0.0f;
    if (isx) xreg = x[((size_t)0 * BATCH + b0 + bb) * INPUT + ii];

    auto WAITC = [&](int c) {
        int s = c % NSLOT;
        wait_parity(mbar_u + s * 8, (par >> s) & 1u);
        par ^= (1u << s);
    };
    auto ISSUE = [&](int n) {
        if (tid == 0)
            for (int q = 0; q < n; q++) issue_chunk_g(Gi + q, ring_u, mbar_u);
        Gi += n;
    };
    auto SLOT = [&](int c) -> const float4* { return ring + (size_t)(c % NSLOT) * CHUNK_F4; };

    auto do_layer = [&](int phase, int l, int w, int c0, const float* in_lo) {
        const ull* bv = bias + ((phase * LAYERS + l) * HID + hh) * 4;
        ull acc[8];
        acc[0] = acc[1] = bv[0];
        acc[2] = acc[3] = bv[1];
        acc[4] = acc[5] = bv[2];
        acc[6] = acc[7] = bv[3];

        if (l == 0) {
            WAITC(c0);     gemv_s<8>(SLOT(c0), in_lo, hh, bg, acc);
            const float* hp = hd + (((w ^ 1) * LAYERS + 0) * HID) * 16;
            WAITC(c0 + 1); gemv_s<32>(SLOT(c0 + 1), hp, hh, bg, acc);
            WAITC(c0 + 2); gemv_s<32>(SLOT(c0 + 2), hp + 32 * 16, hh, bg, acc);
        } else {
            const float* hc = hd + ((w * LAYERS + (l - 1)) * HID) * 16;
            WAITC(c0);     gemv_s<32>(SLOT(c0), hc, hh, bg, acc);
            WAITC(c0 + 1); gemv_s<32>(SLOT(c0 + 1), hc + 32 * 16, hh, bg, acc);
            const float* hp = hd + (((w ^ 1) * LAYERS + l) * HID) * 16;
            WAITC(c0 + 2); gemv_s<32>(SLOT(c0 + 2), hp, hh, bg, acc);
            WAITC(c0 + 3); gemv_s<32>(SLOT(c0 + 3), hp + 32 * 16, hh, bg, acc);
        }

        float2 ai0 = unpk(acc[0]), ai1 = unpk(acc[1]);
        float2 af0 = unpk(acc[2]), af1 = unpk(acc[3]);
        float2 ag0 = unpk(acc[4]), ag1 = unpk(acc[5]);
        float2 ao0 = unpk(acc[6]), ao1 = unpk(acc[7]);
        float ai[4] = {ai0.x, ai0.y, ai1.x, ai1.y};
        float af[4] = {af0.x, af0.y, af1.x, af1.y};
        float ag[4] = {ag0.x, ag0.y, ag1.x, ag1.y};
        float ao[4] = {ao0.x, ao0.y, ao1.x, ao1.y};
        float hout[4];
#pragma unroll
        for (int bi = 0; bi < 4; bi++) {
            float c = fmaf(fsig(af[bi]), c_reg[l][bi], fsig(ai[bi]) * ftanh_(ag[bi]));
            c_reg[l][bi] = c;
            hout[bi] = fsig(ao[bi]) * ftanh_(c);
        }
        float* hrow = hd + ((w * LAYERS + l) * HID + hh) * 16 + bg * 4;
        *(float4*)hrow = make_float4(hout[0], hout[1], hout[2], hout[3]);
        __syncthreads();
        ISSUE(l == 0 ? 3 : 4);
    };

    // -------- encoder --------
    for (int t = 0; t < SEQ_LEN; t++) {
        if (isx) ind[ii * 16 + bb] = xreg;
        __syncthreads();
        if (isx && t + 1 < SEQ_LEN)
            xreg = x[((size_t)(t + 1) * BATCH + b0 + bb) * INPUT + ii];
        int w = t & 1;
        do_layer(0, 0, w, 0, ind);
        do_layer(0, 1, w, 3, ind);
        do_layer(0, 2, w, 7, ind);
        do_layer(0, 3, w, 11, ind);
    }
    // ind still holds x[SEQ_LEN-1] — decoder seed

    // -------- decoder --------
    for (int t = 0; t < TLEN; t++) {
        int w = t & 1;   // (SEQ_LEN + t) & 1 with SEQ_LEN even
        do_layer(1, 0, w, 0, ind);
        do_layer(1, 1, w, 3, ind);
        do_layer(1, 2, w, 7, ind);
        do_layer(1, 3, w, 11, ind);

        if (isx) {
            const float* htop = hd + ((w * LAYERS + (LAYERS - 1)) * HID) * 16;
            float v = lb_s[ii];
#pragma unroll 8
            for (int h2 = 0; h2 < HID; h2++)
                v += lw_s[h2 * INPUT + ii] * htop[h2 * 16 + bb];
            out[((size_t)t * BATCH + b0 + bb) * INPUT + ii] = v;
            ind[ii * 16 + bb] = v;
        }
        __syncthreads();
    }
}

extern "C" void kernel_launch(void* const* d_in, const int* in_sizes, int n_in,
                              void* d_out, int out_size)
{
    const float* x    = (const float*)d_in[0];
    const float* eW0  = (const float*)d_in[1];
    const float* eWih = (const float*)d_in[2];
    const float* eWhh = (const float*)d_in[3];
    const float* eB   = (const float*)d_in[4];
    const float* dW0  = (const float*)d_in[5];
    const float* dWih = (const float*)d_in[6];
    const float* dWhh = (const float*)d_in[7];
    const float* dB   = (const float*)d_in[8];
    const float* linW = (const float*)d_in[9];
    const float* linB = (const float*)d_in[10];
    float* out = (float*)d_out;

    lstm36206574305735_pack<<<240, 256>>>(eW0, eWih, eWhh, dW0, dWih, dWhh);

    cudaFuncSetAttribute(lstm36206574305735_main,
                         cudaFuncAttributeMaxDynamicSharedMemorySize, SMEM_TOTAL_B);
    lstm36206574305735_main<<<NCTA, NTHR, SMEM_TOTAL_B>>>(x, eB, dB, linW, linB, out);
}